// round 16
// baseline (speedup 1.0000x reference)
#include <cuda_runtime.h>
#include <cuda_fp16.h>

#define NUM_POINTS 4
#define NUM_TABLES 10
#define TABLE_SIZE 35
#define LUT_N 65536
#define WCHUNK 256          // float4 per warp-chunk: 32 lanes x 8 batches (16 KB)

__device__ __half g_lut[LUT_N];
__device__ unsigned g_chunk_ctr;

// ---------------------------------------------------------------------------
// Precompute: exact reference fp16 chain for every fp16 bit pattern.
// One entry per thread, 64K threads over 256 CTAs. Also resets the work-steal
// counter (graph-ordered before fplut_main every replay -> idempotent).
// ---------------------------------------------------------------------------
__global__ void build_lut_kernel(const void* __restrict__ cut_raw,
                                 const float* __restrict__ table,
                                 const float* __restrict__ scale)
{
    if (blockIdx.x == 0 && threadIdx.x == 0) g_chunk_ctr = 0;

    unsigned v = blockIdx.x * blockDim.x + threadIdx.x;
    if (v >= LUT_N) return;

    // dtype probe: f32 cut_points -> first word is exactly -65504.0f.
    const float probe = ((const float*)cut_raw)[0];
    const bool cut_is_f32 = (probe < -60000.0f && probe > -70000.0f);

    __half cut[NUM_TABLES + 1];
    #pragma unroll
    for (int i = 0; i <= NUM_TABLES; i++)
        cut[i] = cut_is_f32 ? __float2half(((const float*)cut_raw)[i])
                            : ((const __half*)cut_raw)[i];

    __half xh = __ushort_as_half((unsigned short)v);
    if (__hisnan(xh)) xh = __float2half(0.0f);          // reference NaN -> 0
    if (__hlt(xh, cut[0])) xh = cut[0];
    if (__hgt(xh, cut[NUM_TABLES])) xh = cut[NUM_TABLES];

    // searchsorted(side='right'), ci = clip(ss,1,10)-1
    int ci = 0;
    #pragma unroll
    for (int k = 1; k <= NUM_TABLES - 1; k++)
        if (__hge(xh, cut[k])) ci = k;

    __half dval = __hsub(xh, cut[ci]);
    __half temp = __hmul(dval, __float2half(scale[ci]));
    int idx = (int)__half2float(temp);                  // temp >= 0 -> trunc == floor
    idx = max(0, min(idx, NUM_POINTS));
    if (ci == NUM_TABLES - 1 && idx == 1) idx = 0;
    __half dec = __hsub(temp, __float2half((float)idx));
    int tbl = (ci == 0) ? idx : (1 + (ci - 1) * NUM_POINTS + idx);
    tbl = min(tbl, TABLE_SIZE - 2);
    __half lh = __float2half(table[tbl]);
    __half rh = __float2half(table[tbl + 1]);
    __half y = __hadd(lh, __hmul(__hsub(rh, lh), dec)); // two fp16 roundings
    if (__hle(xh, cut[0])) y = __float2half(table[0]);
    if (__hge(xh, cut[NUM_TABLES])) y = __float2half(table[TABLE_SIZE - 1]);

    g_lut[v] = y;
}

__device__ __forceinline__ unsigned warp_steal() {
    unsigned c = 0;
    if ((threadIdx.x & 31) == 0) c = atomicAdd(&g_chunk_ctr, 1u);
    return __shfl_sync(0xFFFFFFFFu, c, 0);
}

// ---------------------------------------------------------------------------
// Main: per-warp work stealing of 16 KB contiguous chunks. No barriers in the
// steady-state loop; the next chunk id is prefetched before processing the
// current one so the ATOMG latency overlaps the load/gather/store body.
// ---------------------------------------------------------------------------
__global__ __launch_bounds__(1024, 1)
void fplut_main(const float4* __restrict__ x4,
                float4* __restrict__ out4,
                int n4,
                const float* __restrict__ x,
                float* __restrict__ out,
                int n,
                const void* __restrict__ cut_raw)
{
    extern __shared__ __half s_lut[];   // 65536 entries = 128 KB

    // stage LUT: 128 KB / 1024 threads = 8 x uint4 per thread (independent)
    {
        const uint4* src = (const uint4*)g_lut;
        uint4*       dst = (uint4*)s_lut;
        #pragma unroll
        for (int i = threadIdx.x; i < LUT_N * 2 / 16; i += 1024)
            dst[i] = src[i];
    }

    const float probe = ((const float*)cut_raw)[0];
    const bool cut_is_f32 = (probe < -60000.0f && probe > -70000.0f);
    __half c0h, clh;
    if (cut_is_f32) {
        c0h = __float2half(((const float*)cut_raw)[0]);
        clh = __float2half(((const float*)cut_raw)[NUM_TABLES]);
    } else {
        c0h = ((const __half*)cut_raw)[0];
        clh = ((const __half*)cut_raw)[NUM_TABLES];
    }
    const __half2 c0_2 = __half2half2(c0h);
    const __half2 cl_2 = __half2half2(clh);

    __syncthreads();

    const int lane = threadIdx.x & 31;
    const unsigned nw = (unsigned)(n4 / WCHUNK);   // full warp-chunks

    unsigned c = warp_steal();
    while (c < nw) {
        unsigned cn = warp_steal();                // prefetch next id

        const int base = (int)c * WCHUNK + lane;
        float4 vv[8];
        #pragma unroll
        for (int b = 0; b < 8; b++)
            vv[b] = __ldcs(&x4[base + b * 32]);

        #pragma unroll
        for (int b = 0; b < 8; b++) {
            // pack + clip in fp16 SIMD. NaN -> c0 index (LUT[c0]=table[0]=y(0)
            // matches reference NaN->0). f32 overflow -> inf -> clipped here.
            __half2 h01 = __hmin2(__hmax2(__floats2half2_rn(vv[b].x, vv[b].y), c0_2), cl_2);
            __half2 h23 = __hmin2(__hmax2(__floats2half2_rn(vv[b].z, vv[b].w), c0_2), cl_2);
            unsigned b01 = *reinterpret_cast<const unsigned*>(&h01);
            unsigned b23 = *reinterpret_cast<const unsigned*>(&h23);
            float4 r = make_float4(__half2float(s_lut[b01 & 0xFFFFu]),
                                   __half2float(s_lut[b01 >> 16]),
                                   __half2float(s_lut[b23 & 0xFFFFu]),
                                   __half2float(s_lut[b23 >> 16]));
            __stcs(&out4[base + b * 32], r);
        }

        c = cn;
    }

    // remainder float4s not covered by full warp-chunks (none when 256 | n4)
    const int gstride = gridDim.x * blockDim.x;
    for (int i = (int)nw * WCHUNK + blockIdx.x * blockDim.x + threadIdx.x;
         i < n4; i += gstride) {
        float4 v = __ldcs(&x4[i]);
        __half2 h01 = __hmin2(__hmax2(__floats2half2_rn(v.x, v.y), c0_2), cl_2);
        __half2 h23 = __hmin2(__hmax2(__floats2half2_rn(v.z, v.w), c0_2), cl_2);
        unsigned b01 = *reinterpret_cast<const unsigned*>(&h01);
        unsigned b23 = *reinterpret_cast<const unsigned*>(&h23);
        float4 r = make_float4(__half2float(s_lut[b01 & 0xFFFFu]),
                               __half2float(s_lut[b01 >> 16]),
                               __half2float(s_lut[b23 & 0xFFFFu]),
                               __half2float(s_lut[b23 >> 16]));
        __stcs(&out4[i], r);
    }

    // scalar tail (n not multiple of 4); no-op for this problem's shapes
    for (int j = n4 * 4 + blockIdx.x * blockDim.x + threadIdx.x; j < n;
         j += gstride) {
        __half xh = __float2half(fminf(fmaxf(x[j], __half2float(c0h)),
                                       __half2float(clh)));
        out[j] = __half2float(s_lut[(unsigned)__half_as_ushort(xh)]);
    }
}

extern "C" void kernel_launch(void* const* d_in, const int* in_sizes, int n_in,
                              void* d_out, int out_size)
{
    const float* x     = (const float*)d_in[0];
    const void*  cut   = d_in[1];
    const float* table = (const float*)d_in[2];
    const float* scale = (const float*)d_in[3];
    float* out = (float*)d_out;

    int n  = in_sizes[0];
    int n4 = n / 4;

    int sms = 148;
    cudaDeviceGetAttribute(&sms, cudaDevAttrMultiProcessorCount, 0);

    cudaFuncSetAttribute(fplut_main,
                         cudaFuncAttributeMaxDynamicSharedMemorySize,
                         LUT_N * (int)sizeof(__half));

    // 64K threads, one LUT entry each + work-steal counter reset
    build_lut_kernel<<<256, 256>>>(cut, table, scale);
    fplut_main<<<sms, 1024, LUT_N * (int)sizeof(__half)>>>(
        (const float4*)x, (float4*)out, n4, x, out, n, cut);
}

// round 17
// speedup vs baseline: 1.3221x; 1.3221x over previous
#include <cuda_runtime.h>
#include <cuda_fp16.h>

#define NUM_POINTS 4
#define NUM_TABLES 10
#define TABLE_SIZE 35
#define LUT_N 65536
#define CHUNK 8192          // float4 elements per CTA work-steal chunk (512 KB)

__device__ __half g_lut[LUT_N];
__device__ unsigned g_chunk_ctr;

// ---------------------------------------------------------------------------
// Precompute: exact reference fp16 chain for every fp16 bit pattern.
// One entry per thread, 64K threads over 256 CTAs. Also resets the work-steal
// counter (graph-ordered before fplut_main every replay -> idempotent).
// ---------------------------------------------------------------------------
__global__ void build_lut_kernel(const void* __restrict__ cut_raw,
                                 const float* __restrict__ table,
                                 const float* __restrict__ scale)
{
    if (blockIdx.x == 0 && threadIdx.x == 0) g_chunk_ctr = 0;

    unsigned v = blockIdx.x * blockDim.x + threadIdx.x;
    if (v >= LUT_N) return;

    // dtype probe: f32 cut_points -> first word is exactly -65504.0f.
    const float probe = ((const float*)cut_raw)[0];
    const bool cut_is_f32 = (probe < -60000.0f && probe > -70000.0f);

    __half cut[NUM_TABLES + 1];
    #pragma unroll
    for (int i = 0; i <= NUM_TABLES; i++)
        cut[i] = cut_is_f32 ? __float2half(((const float*)cut_raw)[i])
                            : ((const __half*)cut_raw)[i];

    __half xh = __ushort_as_half((unsigned short)v);
    if (__hisnan(xh)) xh = __float2half(0.0f);          // reference NaN -> 0
    if (__hlt(xh, cut[0])) xh = cut[0];
    if (__hgt(xh, cut[NUM_TABLES])) xh = cut[NUM_TABLES];

    // searchsorted(side='right'), ci = clip(ss,1,10)-1
    int ci = 0;
    #pragma unroll
    for (int k = 1; k <= NUM_TABLES - 1; k++)
        if (__hge(xh, cut[k])) ci = k;

    __half dval = __hsub(xh, cut[ci]);
    __half temp = __hmul(dval, __float2half(scale[ci]));
    int idx = (int)__half2float(temp);                  // temp >= 0 -> trunc == floor
    idx = max(0, min(idx, NUM_POINTS));
    if (ci == NUM_TABLES - 1 && idx == 1) idx = 0;
    __half dec = __hsub(temp, __float2half((float)idx));
    int tbl = (ci == 0) ? idx : (1 + (ci - 1) * NUM_POINTS + idx);
    tbl = min(tbl, TABLE_SIZE - 2);
    __half lh = __float2half(table[tbl]);
    __half rh = __float2half(table[tbl + 1]);
    __half y = __hadd(lh, __hmul(__hsub(rh, lh), dec)); // two fp16 roundings
    if (__hle(xh, cut[0])) y = __float2half(table[0]);
    if (__hge(xh, cut[NUM_TABLES])) y = __float2half(table[TABLE_SIZE - 1]);

    g_lut[v] = y;
}

// ---------------------------------------------------------------------------
// Main: persistent CTAs steal contiguous 512 KB chunks (2048 total -- the
// atomic count that measured fastest; per-warp stealing at ~70K atomics
// serialized on the L2 atomic ALU and regressed 25%). The NEXT chunk id is
// grabbed at the top of each chunk so the ATOMG latency overlaps the
// streaming body; one barrier per chunk.
// ---------------------------------------------------------------------------
__global__ __launch_bounds__(1024, 1)
void fplut_main(const float4* __restrict__ x4,
                float4* __restrict__ out4,
                int n4,
                const float* __restrict__ x,
                float* __restrict__ out,
                int n,
                const void* __restrict__ cut_raw)
{
    extern __shared__ __half s_lut[];   // 65536 entries = 128 KB
    __shared__ unsigned s_next;

    // stage LUT: 128 KB / 1024 threads = 8 x uint4 per thread (independent)
    {
        const uint4* src = (const uint4*)g_lut;
        uint4*       dst = (uint4*)s_lut;
        #pragma unroll
        for (int i = threadIdx.x; i < LUT_N * 2 / 16; i += 1024)
            dst[i] = src[i];
    }

    const float probe = ((const float*)cut_raw)[0];
    const bool cut_is_f32 = (probe < -60000.0f && probe > -70000.0f);
    __half c0h, clh;
    if (cut_is_f32) {
        c0h = __float2half(((const float*)cut_raw)[0]);
        clh = __float2half(((const float*)cut_raw)[NUM_TABLES]);
    } else {
        c0h = ((const __half*)cut_raw)[0];
        clh = ((const __half*)cut_raw)[NUM_TABLES];
    }
    const __half2 c0_2 = __half2half2(c0h);
    const __half2 cl_2 = __half2half2(clh);

    const int tid = threadIdx.x;
    const unsigned nchunks = (unsigned)((n4 + CHUNK - 1) / CHUNK);

    // first grab
    if (tid == 0) s_next = atomicAdd(&g_chunk_ctr, 1u);
    __syncthreads();
    unsigned c = s_next;

    while (c < nchunks) {
        // prefetch next chunk id; overlaps with this chunk's processing
        if (tid == 0) s_next = atomicAdd(&g_chunk_ctr, 1u);

        const int base = (int)c * CHUNK + tid;

        if ((int)c * CHUNK + CHUNK <= n4) {
            // full chunk: 8 independent streaming loads in flight per warp
            float4 vv[8];
            #pragma unroll
            for (int b = 0; b < 8; b++)
                vv[b] = __ldcs(&x4[base + b * 1024]);

            #pragma unroll
            for (int b = 0; b < 8; b++) {
                // pack + clip in fp16 SIMD. NaN -> c0 index (LUT[c0]=table[0]
                // = y(0), matching reference NaN->0). f32 overflow -> inf ->
                // clipped here.
                __half2 h01 = __hmin2(__hmax2(__floats2half2_rn(vv[b].x, vv[b].y), c0_2), cl_2);
                __half2 h23 = __hmin2(__hmax2(__floats2half2_rn(vv[b].z, vv[b].w), c0_2), cl_2);
                unsigned b01 = *reinterpret_cast<const unsigned*>(&h01);
                unsigned b23 = *reinterpret_cast<const unsigned*>(&h23);
                float4 r = make_float4(__half2float(s_lut[b01 & 0xFFFFu]),
                                       __half2float(s_lut[b01 >> 16]),
                                       __half2float(s_lut[b23 & 0xFFFFu]),
                                       __half2float(s_lut[b23 >> 16]));
                __stcs(&out4[base + b * 1024], r);
            }
        } else {
            // partial last chunk (not hit for this problem's 2048-chunk split)
            #pragma unroll
            for (int b = 0; b < 8; b++) {
                int i = base + b * 1024;
                if (i < n4) {
                    float4 v = __ldcs(&x4[i]);
                    __half2 h01 = __hmin2(__hmax2(__floats2half2_rn(v.x, v.y), c0_2), cl_2);
                    __half2 h23 = __hmin2(__hmax2(__floats2half2_rn(v.z, v.w), c0_2), cl_2);
                    unsigned b01 = *reinterpret_cast<const unsigned*>(&h01);
                    unsigned b23 = *reinterpret_cast<const unsigned*>(&h23);
                    float4 r = make_float4(__half2float(s_lut[b01 & 0xFFFFu]),
                                           __half2float(s_lut[b01 >> 16]),
                                           __half2float(s_lut[b23 & 0xFFFFu]),
                                           __half2float(s_lut[b23 >> 16]));
                    __stcs(&out4[i], r);
                }
            }
        }

        __syncthreads();        // s_next ready + all threads done with chunk
        c = s_next;
    }

    // scalar tail (n not multiple of 4); no-op for this problem's shapes
    const int gstride = gridDim.x * blockDim.x;
    for (int j = n4 * 4 + blockIdx.x * blockDim.x + tid; j < n; j += gstride) {
        __half xh = __float2half(fminf(fmaxf(x[j], __half2float(c0h)),
                                       __half2float(clh)));
        out[j] = __half2float(s_lut[(unsigned)__half_as_ushort(xh)]);
    }
}

extern "C" void kernel_launch(void* const* d_in, const int* in_sizes, int n_in,
                              void* d_out, int out_size)
{
    const float* x     = (const float*)d_in[0];
    const void*  cut   = d_in[1];
    const float* table = (const float*)d_in[2];
    const float* scale = (const float*)d_in[3];
    float* out = (float*)d_out;

    int n  = in_sizes[0];
    int n4 = n / 4;

    int sms = 148;
    cudaDeviceGetAttribute(&sms, cudaDevAttrMultiProcessorCount, 0);

    cudaFuncSetAttribute(fplut_main,
                         cudaFuncAttributeMaxDynamicSharedMemorySize,
                         LUT_N * (int)sizeof(__half));

    // 64K threads, one LUT entry each + work-steal counter reset
    build_lut_kernel<<<256, 256>>>(cut, table, scale);
    fplut_main<<<sms, 1024, LUT_N * (int)sizeof(__half)>>>(
        (const float4*)x, (float4*)out, n4, x, out, n, cut);
}